// round 16
// baseline (speedup 1.0000x reference)
#include <cuda_runtime.h>
#include <cuda_bf16.h>
#include <cstdint>

// VectorQuantizer: x [32,2048,64] f32, codebook [1024,64] f32
// out f32: quantized [32,64,2048] | loss | indices [32,2048]

#define N_TOK   (32 * 2048)
#define K_CODES 1024
#define D_DIM   64
#define T_LEN   2048
#define LOSS_OFF ((size_t)N_TOK * D_DIM)
#define IDX_OFF  (LOSS_OFF + 1)
#define DELTA    1.5e-3f
#define SE_SCALE ((1.0f / 1024.0f) / 127.0f)    // fixed e int8 scale (|e| < 1/1024)

#define BDIM    128
#define CHUNK   128
#define NCH     (K_CODES / CHUNK)               // 8
#define CWORDS  (CHUNK * 6)                      // uint4 per chunk (96B/code)

// dynamic smem layout (bytes)
#define SM_E0   0                                // 128 x 96B = 12288
#define SM_E1   12288
#define SM_B    24576                            // 1024 f32 = 4096
#define SM_X    28672                            // 128 x 65 f32 = 33280
#define SMEM_SZ 61952

__device__ double g_loss_acc;
__device__ float  g_bsq[K_CODES];
__device__ int    g_flag_cnt;
__device__ int    g_done_blk;
__device__ int    g_flags[N_TOK];
// packed codes: per code 6 uint4 = [2x int8(dims 0-31)][4x bf16x2(dims 32-63)]
__device__ uint4  g_ep4[K_CODES * 6];

#define CP_ASYNC16(dst, src) \
    asm volatile("cp.async.cg.shared.global [%0], [%1], 16;" \
        :: "r"(dst), "l"(__cvta_generic_to_global(src)) : "memory")
#define CP_COMMIT() asm volatile("cp.async.commit_group;" ::: "memory")
#define CP_WAIT1()  asm volatile("cp.async.wait_group 1;" ::: "memory")

__device__ __forceinline__ uint32_t smem_u32(const void* p) {
    uint32_t a;
    asm("{ .reg .u64 t; cvta.to.shared.u64 t, %1; cvt.u32.u64 %0, t; }" : "=r"(a) : "l"(p));
    return a;
}

__device__ __forceinline__ uint32_t pack4(float a, float b, float c, float d, float inv) {
    int i0 = __float2int_rn(a * inv), i1 = __float2int_rn(b * inv);
    int i2 = __float2int_rn(c * inv), i3 = __float2int_rn(d * inv);
    return (uint32_t)(i0 & 0xff) | ((uint32_t)(i1 & 0xff) << 8) |
           ((uint32_t)(i2 & 0xff) << 16) | ((uint32_t)(i3 & 0xff) << 24);
}

__device__ __forceinline__ uint32_t pack_bf2(float a, float b) {
    __nv_bfloat162 h = __float22bfloat162_rn(make_float2(a, b));
    uint32_t u;
    memcpy(&u, &h, 4);
    return u;
}

__device__ __forceinline__ __nv_bfloat162 as_bf2(uint32_t u) {
    __nv_bfloat162 h;
    memcpy(&h, &u, 4);
    return h;
}

// ---------------- prep: init + bsq (reference-exact) + packed e ----------------
__global__ void vq_prep_kernel(const float* __restrict__ cb) {
    int k = blockIdx.x * blockDim.x + threadIdx.x;
    if (k == 0) { g_loss_acc = 0.0; g_flag_cnt = 0; g_done_blk = 0; }
    if (k >= K_CODES) return;
    const float* row = cb + (size_t)k * D_DIM;
    float s = 0.0f;
    #pragma unroll 8
    for (int i = 0; i < D_DIM; i++) s = __fadd_rn(s, __fmul_rn(row[i], row[i]));
    g_bsq[k] = s;
    // int8 part: dims 0..31, fixed scale
    uint4 w0, w1;
    w0.x = pack4(row[0],  row[1],  row[2],  row[3],  1.0f / SE_SCALE);
    w0.y = pack4(row[4],  row[5],  row[6],  row[7],  1.0f / SE_SCALE);
    w0.z = pack4(row[8],  row[9],  row[10], row[11], 1.0f / SE_SCALE);
    w0.w = pack4(row[12], row[13], row[14], row[15], 1.0f / SE_SCALE);
    w1.x = pack4(row[16], row[17], row[18], row[19], 1.0f / SE_SCALE);
    w1.y = pack4(row[20], row[21], row[22], row[23], 1.0f / SE_SCALE);
    w1.z = pack4(row[24], row[25], row[26], row[27], 1.0f / SE_SCALE);
    w1.w = pack4(row[28], row[29], row[30], row[31], 1.0f / SE_SCALE);
    g_ep4[k * 6 + 0] = w0;
    g_ep4[k * 6 + 1] = w1;
    // bf16 part: dims 32..63 raw
    #pragma unroll
    for (int q = 0; q < 4; q++) {
        uint4 w;
        int b = 32 + q * 8;
        w.x = pack_bf2(row[b + 0], row[b + 1]);
        w.y = pack_bf2(row[b + 2], row[b + 3]);
        w.z = pack_bf2(row[b + 4], row[b + 5]);
        w.w = pack_bf2(row[b + 6], row[b + 7]);
        g_ep4[k * 6 + 2 + q] = w;
    }
}

// ---------------- mixed-pipe screen + in-kernel exact resolve ----------------
__global__ __launch_bounds__(BDIM, 3) void vq_screen_kernel(
    const float* __restrict__ x, const float* __restrict__ cb, float* __restrict__ out)
{
    extern __shared__ char smem[];
    __shared__ float s_wl[4];
    const uint32_t sb = smem_u32(smem);
    const int tid  = threadIdx.x;
    const int blk0 = blockIdx.x * BDIM;
    const int tok  = blk0 + tid;

    // prologue: group0 = chunk0 + whole bsq; group1 = chunk1
    #pragma unroll
    for (int u = 0; u < 6; u++)
        CP_ASYNC16(sb + SM_E0 + (tid + u * BDIM) * 16, g_ep4 + tid + u * BDIM);
    #pragma unroll
    for (int u = 0; u < 2; u++)
        CP_ASYNC16(sb + SM_B + (tid + u * BDIM) * 16, g_bsq + (tid + u * BDIM) * 4);
    CP_COMMIT();
    #pragma unroll
    for (int u = 0; u < 6; u++)
        CP_ASYNC16(sb + SM_E1 + (tid + u * BDIM) * 16, g_ep4 + CWORDS + tid + u * BDIM);
    CP_COMMIT();

    // stage x rows into padded smem (coalesced)
    {
        float* sx = (float*)(smem + SM_X);
        #pragma unroll
        for (int u = tid; u < BDIM * D_DIM; u += BDIM) {
            int row = u >> 6, col = u & 63;
            sx[row * 65 + col] = x[(size_t)blk0 * D_DIM + u];
        }
    }

    CP_WAIT1();           // chunk0 + bsq resident (chunk1 may be pending)
    __syncthreads();      // x staging + chunk0 visible

    // ---- per-thread x prep: int8 (dims 0-31) + bf16x2 (dims 32-63) ----
    const float* xrow = (const float*)(smem + SM_X) + tid * 65;
    uint32_t xq[8];
    __nv_bfloat162 xh[16];
    float ns2i;
    {
        float gmax = 0.0f;
        #pragma unroll
        for (int i = 0; i < 32; i++) gmax = fmaxf(gmax, fabsf(xrow[i]));
        gmax = fmaxf(gmax, 1e-20f);
        float inv = 127.0f / gmax;
        #pragma unroll
        for (int j = 0; j < 8; j++)
            xq[j] = pack4(xrow[4 * j + 0], xrow[4 * j + 1],
                          xrow[4 * j + 2], xrow[4 * j + 3], inv);
        ns2i = -2.0f * (gmax / 127.0f) * SE_SCALE;
        #pragma unroll
        for (int j = 0; j < 16; j++)
            xh[j] = __float22bfloat162_rn(make_float2(xrow[32 + 2 * j], xrow[33 + 2 * j]));
    }
    const float* bp = (const float*)(smem + SM_B);

    // candidate ring (last 8 inserts) + running min
    float m1  = 3.402823466e38f;
    float lim = 3.402823466e38f;
    int   rk[8];
    float rf[8];
    #pragma unroll
    for (int j = 0; j < 8; j++) { rk[j] = 0; rf[j] = 3.402823466e38f; }
    int n_ins = 0, cnt_since = 0;

    for (int ch = 0; ch < NCH; ch++) {
        if (ch) { CP_WAIT1(); __syncthreads(); }
        const uint4* ep = (const uint4*)(smem + ((ch & 1) ? SM_E1 : SM_E0));

        #pragma unroll 2
        for (int c = 0; c < CHUNK; c++) {
            const uint4* eb = ep + c * 6;
            uint4 i0 = eb[0];
            uint4 i1 = eb[1];
            uint4 h0 = eb[2];
            uint4 h1 = eb[3];
            uint4 h2 = eb[4];
            uint4 h3 = eb[5];
            // int8 half (dims 0-31): 2 chains of 4 dp4a
            int a0 = __dp4a((int)xq[0], (int)i0.x, 0);
            int a1 = __dp4a((int)xq[1], (int)i0.y, 0);
            a0 = __dp4a((int)xq[2], (int)i0.z, a0);
            a1 = __dp4a((int)xq[3], (int)i0.w, a1);
            a0 = __dp4a((int)xq[4], (int)i1.x, a0);
            a1 = __dp4a((int)xq[5], (int)i1.y, a1);
            a0 = __dp4a((int)xq[6], (int)i1.z, a0);
            a1 = __dp4a((int)xq[7], (int)i1.w, a1);
            int idot = a0 + a1;
            // bf16 half (dims 32-63): 4 chains x (1 hmul + 3 hfma)
            __nv_bfloat162 c0 = __hmul2(xh[0],  as_bf2(h0.x));
            __nv_bfloat162 c1 = __hmul2(xh[1],  as_bf2(h0.y));
            __nv_bfloat162 c2 = __hmul2(xh[2],  as_bf2(h0.z));
            __nv_bfloat162 c3 = __hmul2(xh[3],  as_bf2(h0.w));
            c0 = __hfma2(xh[4],  as_bf2(h1.x), c0);
            c1 = __hfma2(xh[5],  as_bf2(h1.y), c1);
            c2 = __hfma2(xh[6],  as_bf2(h1.z), c2);
            c3 = __hfma2(xh[7],  as_bf2(h1.w), c3);
            c0 = __hfma2(xh[8],  as_bf2(h2.x), c0);
            c1 = __hfma2(xh[9],  as_bf2(h2.y), c1);
            c2 = __hfma2(xh[10], as_bf2(h2.z), c2);
            c3 = __hfma2(xh[11], as_bf2(h2.w), c3);
            c0 = __hfma2(xh[12], as_bf2(h3.x), c0);
            c1 = __hfma2(xh[13], as_bf2(h3.y), c1);
            c2 = __hfma2(xh[14], as_bf2(h3.z), c2);
            c3 = __hfma2(xh[15], as_bf2(h3.w), c3);
            __nv_bfloat162 hs = __hadd2(__hadd2(c0, c1), __hadd2(c2, c3));
            float2 tf = __bfloat1622float2(hs);
            float tail = tf.x + tf.y;
            const int k = ch * CHUNK + c;
            float d = fmaf(ns2i, (float)idot, fmaf(-2.0f, tail, bp[k]));
            if (d < lim) {                       // rare
                #pragma unroll
                for (int j = 7; j > 0; j--) { rk[j] = rk[j-1]; rf[j] = rf[j-1]; }
                rk[0] = k; rf[0] = d;
                n_ins = min(n_ins + 1, 8);
                cnt_since++;
                if (d < m1) { m1 = d; lim = d + DELTA; cnt_since = 0; }
            }
        }

        __syncthreads();   // all warps done with this buffer
        if (ch + 2 < NCH) {
            uint32_t eb = sb + ((ch & 1) ? SM_E1 : SM_E0);
            #pragma unroll
            for (int u = 0; u < 6; u++)
                CP_ASYNC16(eb + (tid + u * BDIM) * 16,
                           g_ep4 + (ch + 2) * CWORDS + tid + u * BDIM);
        }
        CP_COMMIT();       // uniform group count
    }

    // ---- exact resolve over candidates (R1-bitwise arithmetic) ----
    const float4* cb4 = (const float4*)cb;
    int myidx = -1;
    if (cnt_since < 8) {                          // running-min entry still in ring
        float A = 0.0f;
        #pragma unroll
        for (int i = 0; i < D_DIM; i++)
            A = __fadd_rn(A, __fmul_rn(xrow[i], xrow[i]));
        float bestd = 3.402823466e38f; int bestk = 0x7fffffff;
        #pragma unroll
        for (int j = 0; j < 8; j++) {
            if (j < n_ins && rf[j] <= lim) {
                int k = rk[j];
                const float4* er = cb4 + (size_t)k * 16;
                float a0 = 0.f, a1 = 0.f, a2 = 0.f, a3 = 0.f;
                #pragma unroll
                for (int jj = 0; jj < 16; jj++) {
                    float4 ev = er[jj];
                    a0 = fmaf(xrow[4 * jj + 0], ev.x, a0);
                    a1 = fmaf(xrow[4 * jj + 1], ev.y, a1);
                    a2 = fmaf(xrow[4 * jj + 2], ev.z, a2);
                    a3 = fmaf(xrow[4 * jj + 3], ev.w, a3);
                }
                float dot = __fadd_rn(__fadd_rn(a0, a1), __fadd_rn(a2, a3));
                float tv  = __fadd_rn(A, bp[k]);
                float d   = __fadd_rn(tv, -__fmul_rn(2.0f, dot));
                if (d < bestd || (d == bestd && k < bestk)) { bestd = d; bestk = k; }
            }
        }
        myidx = bestk;
    }

    // ---- epilogue ----
    float lsf = 0.0f;
    if (myidx < 0) {
        int pos = atomicAdd(&g_flag_cnt, 1);
        g_flags[pos] = tok;
    } else {
        const int bq = tok >> 11, tq = tok & 2047;
        float* qout = out + ((size_t)bq * D_DIM) * T_LEN + tq;
        const float* er = cb + (size_t)myidx * D_DIM;
        #pragma unroll
        for (int i = 0; i < D_DIM; i++) {
            float xv = xrow[i];
            float dv = __fadd_rn(er[i], -xv);
            lsf = fmaf(dv, dv, lsf);
            qout[(size_t)i * T_LEN] = __fadd_rn(xv, dv);
        }
        out[IDX_OFF + tok] = (float)myidx;
    }
    #pragma unroll
    for (int o = 16; o > 0; o >>= 1)
        lsf += __shfl_down_sync(0xffffffffu, lsf, o);
    if ((tid & 31) == 0) s_wl[tid >> 5] = lsf;
    __syncthreads();
    if (tid == 0) {
        double s = (double)s_wl[0] + (double)s_wl[1] + (double)s_wl[2] + (double)s_wl[3];
        atomicAdd(&g_loss_acc, s);
    }
}

// -------- exact fallback (flagged tokens; expected ~0) + fused finalize --------
#define EX_GRID 64
__global__ __launch_bounds__(128) void vq_exact_kernel(
    const float* __restrict__ x, const float* __restrict__ cb, float* __restrict__ out)
{
    const int cnt = g_flag_cnt;
    __shared__ float sx[8][D_DIM];
    __shared__ int   stok[8];
    const int g = threadIdx.x >> 4, c = threadIdx.x & 15;

    if (blockIdx.x * 8 < cnt) {
        for (int base = blockIdx.x * 8; base < cnt; base += EX_GRID * 8) {
            __syncthreads();
            int slot = base + g;
            if (c == 0) stok[g] = (slot < cnt) ? g_flags[slot] : -1;
            __syncthreads();
            int tok = stok[g];
            if (tok >= 0) {
                #pragma unroll
                for (int i = 0; i < 4; i++) sx[g][c * 4 + i] = x[(size_t)tok * D_DIM + c * 4 + i];
            }
            __syncthreads();

            float best = 3.402823466e38f; int bidx = 0;
            if (tok >= 0) {
                float A = 0.0f;
                #pragma unroll
                for (int i = 0; i < D_DIM; i++) A = __fadd_rn(A, __fmul_rn(sx[g][i], sx[g][i]));
                for (int t = 0; t < K_CODES / 16; t++) {
                    int k = c + 16 * t;
                    const float* e = cb + (size_t)k * D_DIM;
                    float a0 = 0.f, a1 = 0.f, a2 = 0.f, a3 = 0.f;
                    #pragma unroll
                    for (int j = 0; j < 16; j++) {
                        a0 = fmaf(sx[g][4 * j + 0], e[4 * j + 0], a0);
                        a1 = fmaf(sx[g][4 * j + 1], e[4 * j + 1], a1);
                        a2 = fmaf(sx[g][4 * j + 2], e[4 * j + 2], a2);
                        a3 = fmaf(sx[g][4 * j + 3], e[4 * j + 3], a3);
                    }
                    float dot = __fadd_rn(__fadd_rn(a0, a1), __fadd_rn(a2, a3));
                    float tv  = __fadd_rn(A, g_bsq[k]);
                    float d   = __fadd_rn(tv, -__fmul_rn(2.0f, dot));
                    if (d < best) { best = d; bidx = k; }
                }
            }
            #pragma unroll
            for (int o = 8; o > 0; o >>= 1) {
                float ob = __shfl_down_sync(0xffffffffu, best, o, 16);
                int   oi = __shfl_down_sync(0xffffffffu, bidx, o, 16);
                if (ob < best || (ob == best && oi < bidx)) { best = ob; bidx = oi; }
            }
            if (tok >= 0 && c == 0) {
                const int bq = tok >> 11, tq = tok & 2047;
                float* qout = out + ((size_t)bq * D_DIM) * T_LEN + tq;
                const float* er = cb + (size_t)bidx * D_DIM;
                double ls = 0.0;
                #pragma unroll
                for (int i = 0; i < D_DIM; i++) {
                    float xv = sx[g][i];
                    float dv = __fadd_rn(er[i], -xv);
                    ls += (double)dv * dv;
                    qout[(size_t)i * T_LEN] = __fadd_rn(xv, dv);
                }
                out[IDX_OFF + tok] = (float)bidx;
                atomicAdd(&g_loss_acc, ls);
            }
        }
    }

    // fused finalize: last block writes the loss
    __syncthreads();
    if (threadIdx.x == 0) {
        __threadfence();
        int prev = atomicAdd(&g_done_blk, 1);
        if (prev == EX_GRID - 1) {
            double m = g_loss_acc / (double)((size_t)N_TOK * D_DIM);
            out[LOSS_OFF] = (float)(m + 0.25 * m);
        }
    }
}

extern "C" void kernel_launch(void* const* d_in, const int* in_sizes, int n_in,
                              void* d_out, int out_size) {
    const float* x  = (const float*)d_in[0];
    const float* cb = (const float*)d_in[1];
    float* out = (float*)d_out;
    (void)in_sizes; (void)n_in; (void)out_size;

    cudaFuncSetAttribute(vq_screen_kernel, cudaFuncAttributeMaxDynamicSharedMemorySize, SMEM_SZ);

    vq_prep_kernel<<<32, 32>>>(cb);
    vq_screen_kernel<<<N_TOK / BDIM, BDIM, SMEM_SZ>>>(x, cb, out);
    vq_exact_kernel<<<EX_GRID, 128>>>(x, cb, out);
}